// round 11
// baseline (speedup 1.0000x reference)
#include <cuda_runtime.h>
#include <cuda_fp16.h>

// Problem constants (fixed by the dataset; guarded at runtime).
#define NN 100000
#define EE 3200000
#define FF 128
#define F4 (FF / 4)     // 32 float4 per feature row
#define SLOTS 128       // padded edge slots per node (P(deg>128) ~ 1e-40, Poisson(32))
#define NWARPS 8        // warps (dest nodes) per block in SpMM

// ---------------- static scratch (no allocations; zero-init at load) ------
__device__ int    g_cnt[NN];                   // in-degree; re-zeroed in step K
__device__ float  g_dinv[NN];
__device__ int    g_meta[NN * SLOTS];          // BYTE offset of src row (= row*256)
__device__ float4 g_px[NN * F4];               // X' = Dinv*x (fp32 master, P0)
__device__ float4 g_pa[NN * F4];               // fp32 P ping-pong
__device__ float4 g_pb[NN * F4];
__device__ uint2  g_h16a[NN * F4];             // fp16 gather rows (256 B/node)
__device__ uint2  g_h16b[NN * F4];

// ---------------- setup 1: single-pass padded-CSR scatter (4 edges/thread)
__global__ void scatter_k(const int4* __restrict__ row4, const int4* __restrict__ col4,
                          const int* __restrict__ row, const int* __restrict__ col,
                          int E4, int E) {
    int t = blockIdx.x * blockDim.x + threadIdx.x;
    if (t < E4) {
        int4 c = __ldg(&col4[t]);
        int4 r = __ldg(&row4[t]);
        int p0 = atomicAdd(&g_cnt[c.x], 1);
        int p1 = atomicAdd(&g_cnt[c.y], 1);
        int p2 = atomicAdd(&g_cnt[c.z], 1);
        int p3 = atomicAdd(&g_cnt[c.w], 1);
        if (p0 < SLOTS) g_meta[(c.x << 7) + p0] = r.x << 8;
        if (p1 < SLOTS) g_meta[(c.y << 7) + p1] = r.y << 8;
        if (p2 < SLOTS) g_meta[(c.z << 7) + p2] = r.z << 8;
        if (p3 < SLOTS) g_meta[(c.w << 7) + p3] = r.w << 8;
    }
    int rem = E4 * 4 + t;                      // tail (E not multiple of 4)
    if (t < (E & 3) && rem < E) {
        int c = col[rem];
        int pos = atomicAdd(&g_cnt[c], 1);
        if (pos < SLOTS) g_meta[(c << 7) + pos] = row[rem] << 8;
    }
}

// ---------------- setup 2: dinv from counts + prescale X' -----------------
__global__ void prescale_k(const float4* __restrict__ x4, int n) {
    int gid = blockIdx.x * blockDim.x + threadIdx.x;
    int stride = gridDim.x * blockDim.x;

    for (int i = gid; i < n; i += stride) {
        int d = g_cnt[i];
        g_dinv[i] = (d > 0) ? rsqrtf((float)d) : 0.0f;
    }

    // Can't overlap with the loop above (g_dinv read below); grid-stride means
    // a thread may read dinv written by another block -> split via second pass
    // over an independent mapping: j>>5 node's dinv must be final. Use a
    // block-level barrier-free trick: recompute dinv locally instead of reading.
    int total = n * F4;
    for (int j = gid; j < total; j += stride) {
        int node = j >> 5;
        int d = g_cnt[node];
        float s = (d > 0) ? rsqrtf((float)d) : 0.0f;   // recompute: no dependency
        float4 v = x4[j];
        v.x *= s; v.y *= s; v.z *= s; v.w *= s;
        g_px[j] = v;
        __half2 h01 = __floats2half2_rn(v.x, v.y);
        __half2 h23 = __floats2half2_rn(v.z, v.w);
        uint2 u;
        u.x = *(unsigned int*)&h01;
        u.y = *(unsigned int*)&h23;
        g_h16a[j] = u;
    }
}

// ---------------- fused SpMM (fp16 uint4 gather, 2 edges/iter) ------------
// Scaled space: P'_i = Dinv * P_i; gather is unweighted sum over in-edges.
//   step 1:  P'_1 = d2*S;              acc = mf0*X' + w1*P'_1
//   step>=2: P'_i = 2*d2*S - P'_{i-2}; acc += wi*P'_i
//   step K:  out = acc * sqrt(deg); isolated nodes handled analytically;
//            also re-zeroes g_cnt[c] for the next harness call.
__global__ void __launch_bounds__(NWARPS * 32)
spmm_k(const char*   __restrict__ h16,     // fp16 P'_{i-1} base (bytes)
       const float4* __restrict__ pprev2,  // fp32 P'_{i-2} (X' at step 1/2)
       float4*       pout,                 // fp32 P'_i (may alias pprev2; per-thread RMW)
       uint2*        __restrict__ pout16,  // fp16 P'_i
       float4*       __restrict__ acc,
       const float4* __restrict__ x4,
       const float*  __restrict__ mf,
       const float*  __restrict__ lap,
       int step, int K, int n) {
    __shared__ int smeta[NWARPS][32];
    int wid = threadIdx.x >> 5;
    int lane = threadIdx.x & 31;
    int c = blockIdx.x * NWARPS + wid;
    if (c >= n) return;

    int cnt = g_cnt[c];
    if (cnt > SLOTS) cnt = SLOTS;
    int start = c << 7;                        // padded CSR: node c at c*SLOTS
    int end   = start + cnt;

    int half = lane >> 4;                      // which edge of the pair
    const char* hl = h16 + ((lane & 15) << 4); // lane's 16-byte feature slice

    float a0=0.f,a1=0.f,a2=0.f,a3=0.f,a4=0.f,a5=0.f,a6=0.f,a7=0.f;

    for (int base = start; base < end; base += 32) {
        int m = end - base;
        if (m > 32) m = 32;
        if (lane < m) smeta[wid][lane] = g_meta[base + lane];
        __syncwarp();
        int npair = m >> 1;
        #pragma unroll 4
        for (int k = 0; k < npair; k++) {
            int off = smeta[wid][2 * k + half];
            uint4 hv = __ldg((const uint4*)(hl + off));
            float2 f0 = __half22float2(*(const __half2*)&hv.x);
            float2 f1 = __half22float2(*(const __half2*)&hv.y);
            float2 f2 = __half22float2(*(const __half2*)&hv.z);
            float2 f3 = __half22float2(*(const __half2*)&hv.w);
            a0 += f0.x; a1 += f0.y; a2 += f1.x; a3 += f1.y;
            a4 += f2.x; a5 += f2.y; a6 += f3.x; a7 += f3.y;
        }
        if ((m & 1) && half == 0) {
            int off = smeta[wid][m - 1];
            uint4 hv = __ldg((const uint4*)(hl + off));
            float2 f0 = __half22float2(*(const __half2*)&hv.x);
            float2 f1 = __half22float2(*(const __half2*)&hv.y);
            float2 f2 = __half22float2(*(const __half2*)&hv.z);
            float2 f3 = __half22float2(*(const __half2*)&hv.w);
            a0 += f0.x; a1 += f0.y; a2 += f1.x; a3 += f1.y;
            a4 += f2.x; a5 += f2.y; a6 += f3.x; a7 += f3.y;
        }
        __syncwarp();
    }

    // Combine the two edge-halves, then redistribute so lane L owns float4 #L.
    const unsigned FULL = 0xffffffffu;
    a0 += __shfl_xor_sync(FULL, a0, 16);
    a1 += __shfl_xor_sync(FULL, a1, 16);
    a2 += __shfl_xor_sync(FULL, a2, 16);
    a3 += __shfl_xor_sync(FULL, a3, 16);
    a4 += __shfl_xor_sync(FULL, a4, 16);
    a5 += __shfl_xor_sync(FULL, a5, 16);
    a6 += __shfl_xor_sync(FULL, a6, 16);
    a7 += __shfl_xor_sync(FULL, a7, 16);

    int src = lane >> 1;
    float c0 = __shfl_sync(FULL, a0, src);
    float c1 = __shfl_sync(FULL, a1, src);
    float c2 = __shfl_sync(FULL, a2, src);
    float c3 = __shfl_sync(FULL, a3, src);
    float c4 = __shfl_sync(FULL, a4, src);
    float c5 = __shfl_sync(FULL, a5, src);
    float c6 = __shfl_sync(FULL, a6, src);
    float c7 = __shfl_sync(FULL, a7, src);
    bool odd = (lane & 1);
    float sx = odd ? c4 : c0;
    float sy = odd ? c5 : c1;
    float sz = odd ? c6 : c2;
    float sw = odd ? c7 : c3;

    int idx = c * F4 + lane;
    float dinv = g_dinv[c];
    float d2 = dinv * dinv;
    float wi = lap[step - 1] * mf[step];

    float4 p, a;
    if (step == 1) {
        float w0 = mf[0];
        float4 xp = pprev2[idx];              // X'
        p.x = d2 * sx; p.y = d2 * sy; p.z = d2 * sz; p.w = d2 * sw;
        a.x = w0 * xp.x + wi * p.x;
        a.y = w0 * xp.y + wi * p.y;
        a.z = w0 * xp.z + wi * p.z;
        a.w = w0 * xp.w + wi * p.w;
    } else {
        float4 p2 = pprev2[idx];
        float td2 = 2.f * d2;
        p.x = td2 * sx - p2.x;
        p.y = td2 * sy - p2.y;
        p.z = td2 * sz - p2.z;
        p.w = td2 * sw - p2.w;
        a = acc[idx];
        a.x += wi * p.x;
        a.y += wi * p.y;
        a.z += wi * p.z;
        a.w += wi * p.w;
    }

    if (step < K) {
        acc[idx]  = a;
        if (step + 2 <= K) pout[idx] = p;     // fp32 master only if a later step reads it
        __half2 h01 = __floats2half2_rn(p.x, p.y);
        __half2 h23 = __floats2half2_rn(p.z, p.w);
        uint2 u;
        u.x = *(unsigned int*)&h01;
        u.y = *(unsigned int*)&h23;
        pout16[idx] = u;
    } else {
        if (dinv > 0.f) {
            float sd = 1.0f / dinv;           // = sqrt(deg) (+~1ulp, negligible)
            a.x *= sd; a.y *= sd; a.z *= sd; a.w *= sd;
            acc[idx] = a;
        } else {
            // isolated node: P_{2j} = (-1)^j x, P_odd = 0
            float cE = mf[0];
            float sgn = -1.f;
            for (int j = 2; j <= K; j += 2) {
                cE += sgn * lap[j - 1] * mf[j];
                sgn = -sgn;
            }
            float4 xv = x4[idx];
            xv.x *= cE; xv.y *= cE; xv.z *= cE; xv.w *= cE;
            acc[idx] = xv;
        }
        if (lane == 0) g_cnt[c] = 0;          // ready for the next harness call
    }
}

// ---------------- launch ----------------
extern "C" void kernel_launch(void* const* d_in, const int* in_sizes, int n_in,
                              void* d_out, int out_size) {
    const float* x   = (const float*)d_in[0];
    const float* mf  = (const float*)d_in[1];   // (1, K+1, 1)
    const float* lap = (const float*)d_in[2];   // (K+1,)
    const int*   ei  = (const int*)d_in[3];     // (2, E) row-major

    int E = in_sizes[3] / 2;
    int K = in_sizes[2] - 1;
    int n = in_sizes[0] / FF;
    if (n > NN) n = NN;
    if (E > EE) E = EE;
    if (K < 1) K = 1;                           // dataset K=10; guard loop/zeroing

    const int* rowp = ei;
    const int* colp = ei + E;
    float4* out = (float4*)d_out;
    const float4* x4 = (const float4*)x;

    int tb = 256;
    int E4 = E >> 2;

    // 2 setup launches; g_cnt is zero on entry (static init / step-K zeroing).
    scatter_k<<<(E4 + tb - 1) / tb, tb>>>((const int4*)rowp, (const int4*)colp,
                                          rowp, colp, E4, E);
    prescale_k<<<(n * F4 + tb - 1) / tb, tb>>>(x4, n);

    void *px, *pa, *pb, *ha, *hb;
    cudaGetSymbolAddress(&px, g_px);
    cudaGetSymbolAddress(&pa, g_pa);
    cudaGetSymbolAddress(&pb, g_pb);
    cudaGetSymbolAddress(&ha, g_h16a);
    cudaGetSymbolAddress(&hb, g_h16b);

    float4* f32buf[2] = {(float4*)pb, (float4*)pa};   // step i -> f32buf[i&1]
    uint2*  h16buf[2] = {(uint2*)ha, (uint2*)hb};     // P_i (fp16) -> h16buf[i&1]

    int grid = (n + NWARPS - 1) / NWARPS;

    for (int step = 1; step <= K; step++) {
        const char* h16 = (const char*)h16buf[(step - 1) & 1];  // P_{i-1}
        uint2* p16out   = h16buf[step & 1];
        float4* pout    = f32buf[step & 1];
        const float4* pprev2 =
            (step <= 2) ? (const float4*)px                 // X' (P0) for steps 1,2
                        : (const float4*)f32buf[step & 1];  // same-parity buffer (RMW)
        spmm_k<<<grid, NWARPS * 32>>>(h16, pprev2, pout, p16out, out, x4,
                                      mf, lap, step, K, n);
    }
}

// round 12
// speedup vs baseline: 1.5881x; 1.5881x over previous
#include <cuda_runtime.h>
#include <cuda_fp16.h>

// Problem constants (fixed by the dataset; guarded at runtime).
#define NN 100000
#define EE 3200000
#define FF 128
#define F4 (FF / 4)   // 32 float4 per feature row
#define NWARPS 8      // warps (dest nodes) per block in SpMM

// ---------------- static scratch (no allocations; zero-init at load) ------
__device__ int    g_deg[NN];                  // re-zeroed at end of each call
__device__ float  g_dinv[NN];
__device__ float  g_sqd[NN];
__device__ int    g_rowptr[NN + 1];
__device__ int    g_curptr[NN];
__device__ int    g_scan[NN];
__device__ int    g_part[128];
__device__ int    g_meta[EE];                 // src row index, packed CSR by dest
__device__ float4 g_px[NN * F4];              // X' = Dinv*x (fp32 master, P0)
__device__ float4 g_pa[NN * F4];              // fp32 P ping-pong
__device__ float4 g_pb[NN * F4];
__device__ uint2  g_h16a[NN * F4];            // fp16 gather rows (256 B/node)
__device__ uint2  g_h16b[NN * F4];

// ---------------- setup 1: in-degree histogram (4 edges/thread) -----------
__global__ void hist_k(const int4* __restrict__ col4, int E4,
                       const int* __restrict__ col, int E) {
    int t = blockIdx.x * blockDim.x + threadIdx.x;
    if (t < E4) {
        int4 c = __ldg(&col4[t]);
        atomicAdd(&g_deg[c.x], 1);
        atomicAdd(&g_deg[c.y], 1);
        atomicAdd(&g_deg[c.z], 1);
        atomicAdd(&g_deg[c.w], 1);
    }
    int rem = E4 * 4 + t;                     // tail (E not multiple of 4)
    if (t < (E & 3) && rem < E) atomicAdd(&g_deg[col[rem]], 1);
}

// ---------------- setup 2: per-block inclusive scan (shuffle) + dinv/sqd --
__global__ void scan1_k(int n) {
    __shared__ int wsum[32];
    int tid = threadIdx.x, lane = tid & 31, w = tid >> 5;
    int i = blockIdx.x * 1024 + tid;
    int v = (i < n) ? g_deg[i] : 0;
    if (i < n) {
        g_dinv[i] = (v > 0) ? rsqrtf((float)v) : 0.0f;
        g_sqd[i]  = (v > 0) ? sqrtf((float)v)  : 0.0f;
    }
    int s = v;
    #pragma unroll
    for (int o = 1; o < 32; o <<= 1) {
        int t = __shfl_up_sync(0xffffffffu, s, o);
        if (lane >= o) s += t;
    }
    if (lane == 31) wsum[w] = s;
    __syncthreads();
    if (w == 0) {
        int ws = wsum[lane];
        #pragma unroll
        for (int o = 1; o < 32; o <<= 1) {
            int t = __shfl_up_sync(0xffffffffu, ws, o);
            if (lane >= o) ws += t;
        }
        wsum[lane] = ws;
    }
    __syncthreads();
    int incl = s + ((w > 0) ? wsum[w - 1] : 0);
    if (i < n) g_scan[i] = incl;
    if (tid == 1023) g_part[blockIdx.x] = incl;
}

// ---------------- setup 3: finalize rowptr/curptr + prescale X' -----------
__global__ void finalize_k(const float4* __restrict__ x4, int n, int E) {
    int gid = blockIdx.x * blockDim.x + threadIdx.x;
    int stride = gridDim.x * blockDim.x;

    if (gid < n) {
        int blk = gid >> 10;
        int pre = 0;
        for (int b = 0; b < blk; b++) pre += g_part[b];   // small, L1-cached
        int excl = g_scan[gid] - g_deg[gid] + pre;
        g_rowptr[gid] = excl;
        g_curptr[gid] = excl;
        if (gid == 0) g_rowptr[n] = E;
    }

    int total = n * F4;
    for (int j = gid; j < total; j += stride) {
        float s = g_dinv[j >> 5];
        float4 v = x4[j];
        v.x *= s; v.y *= s; v.z *= s; v.w *= s;
        g_px[j] = v;
        __half2 h01 = __floats2half2_rn(v.x, v.y);
        __half2 h23 = __floats2half2_rn(v.z, v.w);
        uint2 u;
        u.x = *(unsigned int*)&h01;
        u.y = *(unsigned int*)&h23;
        g_h16a[j] = u;
    }
}

// ---------------- setup 4: scatter (4 edges/thread) + re-zero deg ---------
__global__ void scatter_k(const int4* __restrict__ row4, const int4* __restrict__ col4,
                          const int* __restrict__ row, const int* __restrict__ col,
                          int E4, int E, int n) {
    int t = blockIdx.x * blockDim.x + threadIdx.x;
    int stride = gridDim.x * blockDim.x;

    if (t < E4) {
        int4 c = __ldg(&col4[t]);
        int4 r = __ldg(&row4[t]);
        int p0 = atomicAdd(&g_curptr[c.x], 1);
        int p1 = atomicAdd(&g_curptr[c.y], 1);
        int p2 = atomicAdd(&g_curptr[c.z], 1);
        int p3 = atomicAdd(&g_curptr[c.w], 1);
        g_meta[p0] = r.x;
        g_meta[p1] = r.y;
        g_meta[p2] = r.z;
        g_meta[p3] = r.w;
    }
    int rem = E4 * 4 + t;
    if (t < (E & 3) && rem < E) {
        int pos = atomicAdd(&g_curptr[col[rem]], 1);
        g_meta[pos] = row[rem];
    }
    for (int j = t; j < n; j += stride) g_deg[j] = 0;   // ready for next call
}

// ---------------- fused SpMM (fp16 uint2 gather, 1 edge/iter — R3 body) ---
// Scaled space: P'_i = Dinv * P_i; gather is unweighted sum over in-edges.
//   step 1:  P'_1 = d2*S;              acc = mf0*X' + w1*P'_1
//   step>=2: P'_i = 2*d2*S - P'_{i-2}; acc += wi*P'_i
//   step K:  out = acc * sqrt(deg); isolated nodes handled analytically.
__global__ void __launch_bounds__(NWARPS * 32)
spmm_k(const uint2*  __restrict__ h16,     // fp16 P'_{i-1} (gather source)
       const float4* __restrict__ pprev2,  // fp32 P'_{i-2} (X' at step 1/2)
       float4*       pout,                 // fp32 P'_i (may alias pprev2; per-thread RMW)
       uint2*        __restrict__ pout16,  // fp16 P'_i
       float4*       __restrict__ acc,
       const float4* __restrict__ x4,
       const float*  __restrict__ mf,
       const float*  __restrict__ lap,
       int step, int K, int n) {
    __shared__ int smeta[NWARPS][32];
    int wid = threadIdx.x >> 5;
    int lane = threadIdx.x & 31;
    int c = blockIdx.x * NWARPS + wid;
    if (c >= n) return;

    int start = g_rowptr[c];
    int end   = g_rowptr[c + 1];

    float sx = 0.f, sy = 0.f, sz = 0.f, sw = 0.f;

    for (int base = start; base < end; base += 32) {
        int m = end - base;
        if (m > 32) m = 32;
        if (lane < m) smeta[wid][lane] = g_meta[base + lane];
        __syncwarp();
        #pragma unroll 8
        for (int k = 0; k < m; k++) {
            int r = smeta[wid][k];
            uint2 hv = __ldg(&h16[r * F4 + lane]);
            float2 fa = __half22float2(*(const __half2*)&hv.x);
            float2 fb = __half22float2(*(const __half2*)&hv.y);
            sx += fa.x; sy += fa.y; sz += fb.x; sw += fb.y;
        }
        __syncwarp();
    }

    int idx = c * F4 + lane;
    float dinv = g_dinv[c];
    float d2 = dinv * dinv;
    float wi = lap[step - 1] * mf[step];

    float4 p, a;
    if (step == 1) {
        float w0 = mf[0];
        float4 xp = pprev2[idx];              // X'
        p.x = d2 * sx; p.y = d2 * sy; p.z = d2 * sz; p.w = d2 * sw;
        a.x = w0 * xp.x + wi * p.x;
        a.y = w0 * xp.y + wi * p.y;
        a.z = w0 * xp.z + wi * p.z;
        a.w = w0 * xp.w + wi * p.w;
    } else {
        float4 p2 = pprev2[idx];
        float td2 = 2.f * d2;
        p.x = td2 * sx - p2.x;
        p.y = td2 * sy - p2.y;
        p.z = td2 * sz - p2.z;
        p.w = td2 * sw - p2.w;
        a = acc[idx];
        a.x += wi * p.x;
        a.y += wi * p.y;
        a.z += wi * p.z;
        a.w += wi * p.w;
    }

    if (step < K) {
        acc[idx] = a;
        if (step + 2 <= K) pout[idx] = p;     // fp32 master only if a later step reads it
        __half2 h01 = __floats2half2_rn(p.x, p.y);
        __half2 h23 = __floats2half2_rn(p.z, p.w);
        uint2 u;
        u.x = *(unsigned int*)&h01;
        u.y = *(unsigned int*)&h23;
        pout16[idx] = u;
    } else {
        float sd = g_sqd[c];
        if (sd > 0.f) {
            a.x *= sd; a.y *= sd; a.z *= sd; a.w *= sd;
            acc[idx] = a;
        } else {
            // isolated node: P_{2j} = (-1)^j x, P_odd = 0
            float cE = mf[0];
            float sgn = -1.f;
            for (int j = 2; j <= K; j += 2) {
                cE += sgn * lap[j - 1] * mf[j];
                sgn = -sgn;
            }
            float4 xv = x4[idx];
            xv.x *= cE; xv.y *= cE; xv.z *= cE; xv.w *= cE;
            acc[idx] = xv;
        }
    }
}

// ---------------- launch ----------------
extern "C" void kernel_launch(void* const* d_in, const int* in_sizes, int n_in,
                              void* d_out, int out_size) {
    const float* x   = (const float*)d_in[0];
    const float* mf  = (const float*)d_in[1];   // (1, K+1, 1)
    const float* lap = (const float*)d_in[2];   // (K+1,)
    const int*   ei  = (const int*)d_in[3];     // (2, E) row-major

    int E = in_sizes[3] / 2;
    int K = in_sizes[2] - 1;
    int n = in_sizes[0] / FF;
    if (n > NN) n = NN;
    if (E > EE) E = EE;

    const int* rowp = ei;
    const int* colp = ei + E;
    float4* out = (float4*)d_out;
    const float4* x4 = (const float4*)x;

    int tb = 256;
    int nb = (n + 1023) / 1024;
    int E4 = E >> 2;

    // 4 setup launches; g_deg is zero on entry (static init / prev call end).
    hist_k<<<(E4 + tb - 1) / tb, tb>>>((const int4*)colp, E4, colp, E);
    scan1_k<<<nb, 1024>>>(n);
    finalize_k<<<(n * F4 + tb - 1) / tb, tb>>>(x4, n, E);
    scatter_k<<<(E4 + tb - 1) / tb, tb>>>((const int4*)rowp, (const int4*)colp,
                                          rowp, colp, E4, E, n);

    void *px, *pa, *pb, *ha, *hb;
    cudaGetSymbolAddress(&px, g_px);
    cudaGetSymbolAddress(&pa, g_pa);
    cudaGetSymbolAddress(&pb, g_pb);
    cudaGetSymbolAddress(&ha, g_h16a);
    cudaGetSymbolAddress(&hb, g_h16b);

    float4* f32buf[2] = {(float4*)pb, (float4*)pa};   // step i -> f32buf[i&1]
    uint2*  h16buf[2] = {(uint2*)ha, (uint2*)hb};     // P_i (fp16) -> h16buf[i&1]

    int grid = (n + NWARPS - 1) / NWARPS;

    for (int step = 1; step <= K; step++) {
        const uint2* h16 = h16buf[(step - 1) & 1];     // P_{i-1}
        uint2* p16out    = h16buf[step & 1];
        float4* pout     = f32buf[step & 1];
        const float4* pprev2 =
            (step <= 2) ? (const float4*)px                 // X' (P0) for steps 1,2
                        : (const float4*)f32buf[step & 1];  // same-parity buffer (RMW)
        spmm_k<<<grid, NWARPS * 32>>>(h16, pprev2, pout, p16out, out, x4,
                                      mf, lap, step, K, n);
    }
}

// round 13
// speedup vs baseline: 1.5906x; 1.0015x over previous
#include <cuda_runtime.h>
#include <cuda_fp16.h>

// Problem constants (fixed by the dataset; guarded at runtime).
#define NN 100000
#define EE 3200000
#define FF 128
#define F4 (FF / 4)   // 32 float4 per feature row
#define NWARPS 8      // warps (dest nodes) per block in SpMM

// ---------------- static scratch (no allocations; zero-init at load) ------
__device__ int    g_deg[NN];                  // re-zeroed in spmm step K
__device__ float  g_dinv[NN];
__device__ float  g_sqd[NN];
__device__ int    g_rowptr[NN + 1];
__device__ int    g_curptr[NN];
__device__ int    g_scan[NN];
__device__ int    g_part[128];
__device__ int    g_meta[EE];                 // src row index, packed CSR by dest
__device__ float4 g_px[NN * F4];              // X' = Dinv*x (fp32 master, P0)
__device__ float4 g_pa[NN * F4];              // fp32 P ping-pong
__device__ float4 g_pb[NN * F4];
__device__ uint2  g_h16a[NN * F4];            // fp16 gather rows (256 B/node)
__device__ uint2  g_h16b[NN * F4];

// ---------------- setup 1: in-degree histogram (4 edges/thread) -----------
__global__ void hist_k(const int4* __restrict__ col4, int E4,
                       const int* __restrict__ col, int E) {
    int t = blockIdx.x * blockDim.x + threadIdx.x;
    if (t < E4) {
        int4 c = __ldg(&col4[t]);
        atomicAdd(&g_deg[c.x], 1);
        atomicAdd(&g_deg[c.y], 1);
        atomicAdd(&g_deg[c.z], 1);
        atomicAdd(&g_deg[c.w], 1);
    }
    int rem = E4 * 4 + t;                     // tail (E not multiple of 4)
    if (t < (E & 3) && rem < E) atomicAdd(&g_deg[col[rem]], 1);
}

// ---------------- setup 2: per-block inclusive scan (shuffle) + dinv/sqd --
__global__ void scan1_k(int n) {
    __shared__ int wsum[32];
    int tid = threadIdx.x, lane = tid & 31, w = tid >> 5;
    int i = blockIdx.x * 1024 + tid;
    int v = (i < n) ? g_deg[i] : 0;
    if (i < n) {
        g_dinv[i] = (v > 0) ? rsqrtf((float)v) : 0.0f;
        g_sqd[i]  = (v > 0) ? sqrtf((float)v)  : 0.0f;
    }
    int s = v;
    #pragma unroll
    for (int o = 1; o < 32; o <<= 1) {
        int t = __shfl_up_sync(0xffffffffu, s, o);
        if (lane >= o) s += t;
    }
    if (lane == 31) wsum[w] = s;
    __syncthreads();
    if (w == 0) {
        int ws = wsum[lane];
        #pragma unroll
        for (int o = 1; o < 32; o <<= 1) {
            int t = __shfl_up_sync(0xffffffffu, ws, o);
            if (lane >= o) ws += t;
        }
        wsum[lane] = ws;
    }
    __syncthreads();
    int incl = s + ((w > 0) ? wsum[w - 1] : 0);
    if (i < n) g_scan[i] = incl;
    if (tid == 1023) g_part[blockIdx.x] = incl;
}

// ---------------- setup 3a (stream A): rowptr/curptr ----------------------
__global__ void rowptr_k(int n, int E) {
    int gid = blockIdx.x * blockDim.x + threadIdx.x;
    if (gid < n) {
        int blk = gid >> 10;
        int pre = 0;
        for (int b = 0; b < blk; b++) pre += g_part[b];   // small, L1-cached
        int excl = g_scan[gid] - g_deg[gid] + pre;
        g_rowptr[gid] = excl;
        g_curptr[gid] = excl;
        if (gid == 0) g_rowptr[n] = E;
    }
}

// ---------------- setup 3b (stream B, overlapped): prescale X' ------------
__global__ void prescale_k(const float4* __restrict__ x4, int n) {
    int gid = blockIdx.x * blockDim.x + threadIdx.x;
    int stride = gridDim.x * blockDim.x;
    int total = n * F4;
    for (int j = gid; j < total; j += stride) {
        float s = g_dinv[j >> 5];
        float4 v = x4[j];
        v.x *= s; v.y *= s; v.z *= s; v.w *= s;
        g_px[j] = v;
        __half2 h01 = __floats2half2_rn(v.x, v.y);
        __half2 h23 = __floats2half2_rn(v.z, v.w);
        uint2 u;
        u.x = *(unsigned int*)&h01;
        u.y = *(unsigned int*)&h23;
        g_h16a[j] = u;
    }
}

// ---------------- setup 4 (stream A): scatter (4 edges/thread) ------------
__global__ void scatter_k(const int4* __restrict__ row4, const int4* __restrict__ col4,
                          const int* __restrict__ row, const int* __restrict__ col,
                          int E4, int E) {
    int t = blockIdx.x * blockDim.x + threadIdx.x;
    if (t < E4) {
        int4 c = __ldg(&col4[t]);
        int4 r = __ldg(&row4[t]);
        int p0 = atomicAdd(&g_curptr[c.x], 1);
        int p1 = atomicAdd(&g_curptr[c.y], 1);
        int p2 = atomicAdd(&g_curptr[c.z], 1);
        int p3 = atomicAdd(&g_curptr[c.w], 1);
        g_meta[p0] = r.x;
        g_meta[p1] = r.y;
        g_meta[p2] = r.z;
        g_meta[p3] = r.w;
    }
    int rem = E4 * 4 + t;
    if (t < (E & 3) && rem < E) {
        int pos = atomicAdd(&g_curptr[col[rem]], 1);
        g_meta[pos] = row[rem];
    }
}

// ---------------- fused SpMM (fp16 uint2 gather, 1 edge/iter) -------------
// Scaled space: P'_i = Dinv * P_i; gather is unweighted sum over in-edges.
//   step 1:  P'_1 = d2*S;              acc = mf0*X' + w1*P'_1
//   step>=2: P'_i = 2*d2*S - P'_{i-2}; acc += wi*P'_i
//   step K:  out = acc * sqrt(deg); isolated nodes analytic; re-zeroes g_deg.
__global__ void __launch_bounds__(NWARPS * 32)
spmm_k(const uint2*  __restrict__ h16,     // fp16 P'_{i-1} (gather source)
       const float4* __restrict__ pprev2,  // fp32 P'_{i-2} (X' at step 1/2)
       float4*       pout,                 // fp32 P'_i (may alias pprev2; per-thread RMW)
       uint2*        __restrict__ pout16,  // fp16 P'_i
       float4*       __restrict__ acc,
       const float4* __restrict__ x4,
       const float*  __restrict__ mf,
       const float*  __restrict__ lap,
       int step, int K, int n) {
    __shared__ int smeta[NWARPS][32];
    int wid = threadIdx.x >> 5;
    int lane = threadIdx.x & 31;
    int c = blockIdx.x * NWARPS + wid;
    if (c >= n) return;

    int start = g_rowptr[c];
    int end   = g_rowptr[c + 1];

    float sx = 0.f, sy = 0.f, sz = 0.f, sw = 0.f;

    for (int base = start; base < end; base += 32) {
        int m = end - base;
        if (m > 32) m = 32;
        if (lane < m) smeta[wid][lane] = g_meta[base + lane];
        __syncwarp();
        #pragma unroll 8
        for (int k = 0; k < m; k++) {
            int r = smeta[wid][k];
            uint2 hv = __ldg(&h16[r * F4 + lane]);
            float2 fa = __half22float2(*(const __half2*)&hv.x);
            float2 fb = __half22float2(*(const __half2*)&hv.y);
            sx += fa.x; sy += fa.y; sz += fb.x; sw += fb.y;
        }
        __syncwarp();
    }

    int idx = c * F4 + lane;
    float dinv = g_dinv[c];
    float d2 = dinv * dinv;
    float wi = lap[step - 1] * mf[step];

    float4 p, a;
    if (step == 1) {
        float w0 = mf[0];
        float4 xp = pprev2[idx];              // X'
        p.x = d2 * sx; p.y = d2 * sy; p.z = d2 * sz; p.w = d2 * sw;
        a.x = w0 * xp.x + wi * p.x;
        a.y = w0 * xp.y + wi * p.y;
        a.z = w0 * xp.z + wi * p.z;
        a.w = w0 * xp.w + wi * p.w;
    } else {
        float4 p2 = pprev2[idx];
        float td2 = 2.f * d2;
        p.x = td2 * sx - p2.x;
        p.y = td2 * sy - p2.y;
        p.z = td2 * sz - p2.z;
        p.w = td2 * sw - p2.w;
        a = acc[idx];
        a.x += wi * p.x;
        a.y += wi * p.y;
        a.z += wi * p.z;
        a.w += wi * p.w;
    }

    if (step < K) {
        acc[idx] = a;
        if (step + 2 <= K) pout[idx] = p;     // fp32 master only if a later step reads it
        __half2 h01 = __floats2half2_rn(p.x, p.y);
        __half2 h23 = __floats2half2_rn(p.z, p.w);
        uint2 u;
        u.x = *(unsigned int*)&h01;
        u.y = *(unsigned int*)&h23;
        pout16[idx] = u;
    } else {
        float sd = g_sqd[c];
        if (sd > 0.f) {
            a.x *= sd; a.y *= sd; a.z *= sd; a.w *= sd;
            acc[idx] = a;
        } else {
            // isolated node: P_{2j} = (-1)^j x, P_odd = 0
            float cE = mf[0];
            float sgn = -1.f;
            for (int j = 2; j <= K; j += 2) {
                cE += sgn * lap[j - 1] * mf[j];
                sgn = -sgn;
            }
            float4 xv = x4[idx];
            xv.x *= cE; xv.y *= cE; xv.z *= cE; xv.w *= cE;
            acc[idx] = xv;
        }
        if (lane == 0) g_deg[c] = 0;          // ready for the next harness call
    }
}

// ---------------- launch ----------------
extern "C" void kernel_launch(void* const* d_in, const int* in_sizes, int n_in,
                              void* d_out, int out_size) {
    const float* x   = (const float*)d_in[0];
    const float* mf  = (const float*)d_in[1];   // (1, K+1, 1)
    const float* lap = (const float*)d_in[2];   // (K+1,)
    const int*   ei  = (const int*)d_in[3];     // (2, E) row-major

    int E = in_sizes[3] / 2;
    int K = in_sizes[2] - 1;
    int n = in_sizes[0] / FF;
    if (n > NN) n = NN;
    if (E > EE) E = EE;
    if (K < 1) K = 1;

    const int* rowp = ei;
    const int* colp = ei + E;
    float4* out = (float4*)d_out;
    const float4* x4 = (const float4*)x;

    int tb = 256;
    int nb = (n + 1023) / 1024;
    int E4 = E >> 2;

    // One side stream + events, created once (host-side objects only).
    static cudaStream_t sB = nullptr;
    static cudaEvent_t evFork = nullptr, evJoin = nullptr;
    if (sB == nullptr) {
        cudaStreamCreateWithFlags(&sB, cudaStreamNonBlocking);
        cudaEventCreateWithFlags(&evFork, cudaEventDisableTiming);
        cudaEventCreateWithFlags(&evJoin, cudaEventDisableTiming);
    }

    // Stream A = default (capture) stream.
    hist_k<<<(E4 + tb - 1) / tb, tb>>>((const int4*)colp, E4, colp, E);
    scan1_k<<<nb, 1024>>>(n);

    // Fork: prescale (needs only dinv from scan1) overlaps rowptr+scatter.
    cudaEventRecord(evFork, 0);
    cudaStreamWaitEvent(sB, evFork, 0);
    prescale_k<<<(n * F4 + tb - 1) / tb, tb, 0, sB>>>(x4, n);
    cudaEventRecord(evJoin, sB);

    rowptr_k<<<(n + tb - 1) / tb, tb>>>(n, E);
    scatter_k<<<(E4 + tb - 1) / tb, tb>>>((const int4*)rowp, (const int4*)colp,
                                          rowp, colp, E4, E);
    cudaStreamWaitEvent(0, evJoin, 0);        // join before step 1

    void *px, *pa, *pb, *ha, *hb;
    cudaGetSymbolAddress(&px, g_px);
    cudaGetSymbolAddress(&pa, g_pa);
    cudaGetSymbolAddress(&pb, g_pb);
    cudaGetSymbolAddress(&ha, g_h16a);
    cudaGetSymbolAddress(&hb, g_h16b);

    float4* f32buf[2] = {(float4*)pb, (float4*)pa};   // step i -> f32buf[i&1]
    uint2*  h16buf[2] = {(uint2*)ha, (uint2*)hb};     // P_i (fp16) -> h16buf[i&1]

    int grid = (n + NWARPS - 1) / NWARPS;

    for (int step = 1; step <= K; step++) {
        const uint2* h16 = h16buf[(step - 1) & 1];     // P_{i-1}
        uint2* p16out    = h16buf[step & 1];
        float4* pout     = f32buf[step & 1];
        const float4* pprev2 =
            (step <= 2) ? (const float4*)px                 // X' (P0) for steps 1,2
                        : (const float4*)f32buf[step & 1];  // same-parity buffer (RMW)
        spmm_k<<<grid, NWARPS * 32>>>(h16, pprev2, pout, p16out, out, x4,
                                      mf, lap, step, K, n);
    }
}